// round 1
// baseline (speedup 1.0000x reference)
#include <cuda_runtime.h>

#define NB 64
#define NS 256
#define NI 256
#define NHH 512
#define N2H 1024
#define NM (NB*NS)

// Scratch for the pre-activation GEMM output i = x @ W^T   [16384 x 1024], 64MB
static __device__ float g_C[(size_t)NM * N2H];

typedef unsigned long long u64;
__device__ __forceinline__ u64 pk2(float lo, float hi){ u64 r; asm("mov.b64 %0,{%1,%2};" : "=l"(r) : "f"(lo), "f"(hi)); return r; }
__device__ __forceinline__ void up2(u64 a, float& lo, float& hi){ asm("mov.b64 {%0,%1},%2;" : "=f"(lo), "=f"(hi) : "l"(a)); }
__device__ __forceinline__ u64 fma2(u64 a, u64 b, u64 c){ u64 d; asm("fma.rn.f32x2 %0,%1,%2,%3;" : "=l"(d) : "l"(a), "l"(b), "l"(c)); return d; }
__device__ __forceinline__ u64 mul2(u64 a, u64 b){ u64 d; asm("mul.rn.f32x2 %0,%1,%2;" : "=l"(d) : "l"(a), "l"(b)); return d; }
__device__ __forceinline__ u64 add2(u64 a, u64 b){ u64 d; asm("add.rn.f32x2 %0,%1,%2;" : "=l"(d) : "l"(a), "l"(b)); return d; }

union F4U { float4 f; u64 u[2]; };

// ---------------------------------------------------------------------------
// Kernel 1: SGEMM  C[m][n] = sum_k x[m][k] * W[n][k]
// M=16384, N=1024, K=256.  128x128 tile, BK=32, 256 threads, 8x8 per thread.
// ---------------------------------------------------------------------------
#define BM 128
#define BN 128
#define BK 32

__global__ __launch_bounds__(256) void sgemm_kernel(const float* __restrict__ A,
                                                    const float* __restrict__ W)
{
    __shared__ float As[BK][BM+4];
    __shared__ float Bs[BK][BN+4];
    const int tid = threadIdx.x;
    const int m0 = blockIdx.y * BM;
    const int n0 = blockIdx.x * BN;
    const int tr = tid >> 4;        // 0..15
    const int tc = tid & 15;        // 0..15

    float acc[8][8];
    #pragma unroll
    for (int i=0;i<8;i++)
        #pragma unroll
        for (int j=0;j<8;j++) acc[i][j]=0.f;

    const int lr = tid >> 3;          // 0..31
    const int lc = (tid & 7) << 2;    // 0,4,...,28

    for (int k0=0; k0<NI; k0+=BK){
        #pragma unroll
        for (int h=0; h<4; h++){
            int r = lr + h*32;
            float4 av = *(const float4*)(A + (size_t)(m0+r)*NI + k0 + lc);
            As[lc+0][r]=av.x; As[lc+1][r]=av.y; As[lc+2][r]=av.z; As[lc+3][r]=av.w;
            float4 bv = *(const float4*)(W + (size_t)(n0+r)*NI + k0 + lc);
            Bs[lc+0][r]=bv.x; Bs[lc+1][r]=bv.y; Bs[lc+2][r]=bv.z; Bs[lc+3][r]=bv.w;
        }
        __syncthreads();
        #pragma unroll
        for (int kk=0;kk<BK;kk++){
            float a[8], bb[8];
            *(float4*)(a)    = *(const float4*)(&As[kk][tr*8]);
            *(float4*)(a+4)  = *(const float4*)(&As[kk][tr*8+4]);
            *(float4*)(bb)   = *(const float4*)(&Bs[kk][tc*8]);
            *(float4*)(bb+4) = *(const float4*)(&Bs[kk][tc*8+4]);
            #pragma unroll
            for (int i=0;i<8;i++)
                #pragma unroll
                for (int j=0;j<8;j++)
                    acc[i][j] = fmaf(a[i], bb[j], acc[i][j]);
        }
        __syncthreads();
    }
    #pragma unroll
    for (int i=0;i<8;i++){
        float* cptr = g_C + (size_t)(m0 + tr*8 + i)*N2H + n0 + tc*8;
        *(float4*)(cptr)   = make_float4(acc[i][0],acc[i][1],acc[i][2],acc[i][3]);
        *(float4*)(cptr+4) = make_float4(acc[i][4],acc[i][5],acc[i][6],acc[i][7]);
    }
}

// ---------------------------------------------------------------------------
// Kernel 2: k-trace precompute. Per (b,h): ks recurrence + tanh -> keys output.
// keys_seq[b][t][h] = tanh(ks),  ks = alpha*ks + ik[b][t][h]
// ---------------------------------------------------------------------------
__global__ __launch_bounds__(256) void trace_kernel(float* __restrict__ keys_out)
{
    int gid = blockIdx.x*blockDim.x + threadIdx.x;   // 0..32767
    int b = gid >> 9;
    int h = gid & 511;
    const float* c = g_C + (size_t)b*NS*N2H + h;      // ik column
    float* ko = keys_out + (size_t)b*NS*NHH + h;
    const float ALPHA = 0.9048374180359595f;
    float ks = 0.f;
    #pragma unroll 8
    for (int t=0;t<NS;t++){
        ks = fmaf(ks, ALPHA, __ldg(c + (size_t)t*N2H));
        ko[(size_t)t*NHH] = tanhf(ks);
    }
}

// ---------------------------------------------------------------------------
// Kernel 3: main recurrence. One warp owns 2 mem rows (16 floats/lane each,
// in registers). kt' state kept in registers (kt' = kt/(1-d)).
// Per step: dot(mem_row, k_t) -> butterfly allreduce -> scalar chain ->
// rank-1 row update, all in fma.rn.f32x2.
// Grid: (32 row-groups, 64 batches), 256 threads (8 warps x 2 rows = 16 rows).
// ---------------------------------------------------------------------------
__global__ __launch_bounds__(256) void recur_kernel(const float* __restrict__ keys,
                                                    float* __restrict__ mem_out,
                                                    float* __restrict__ vals_out)
{
    const int b    = blockIdx.y;
    const int rg   = blockIdx.x;
    const int warp = threadIdx.x >> 5;
    const int lane = threadIdx.x & 31;
    const int row0 = rg*16 + warp*2;

    const float ALPHA = 0.9048374180359595f;   // exp(-1/10)
    const float DEC   = 0.9512294245007140f;   // exp(-1/20)
    const float OMD   = 0.0487705754992860f;   // 1 - DEC
    const float LR    = 0.01f;

    u64 m0[8], m1[8], kt[8];
    #pragma unroll
    for (int p=0;p<8;p++){ m0[p]=0ULL; m1[p]=0ULL; kt[p]=0ULL; }

    float vs0=0.f, vs1=0.f, vt0=0.f, vt1=0.f;

    // lane owns j in { c*128 + lane*4 + q : c=0..3, q=0..3 }
    const float4* kb = (const float4*)(keys + (size_t)b*NS*NHH) + lane;
    const float* ivb = g_C + (size_t)b*NS*N2H + NHH + row0;   // iv columns
    float* vb = vals_out + (size_t)b*NS*NHH + row0;

    const u64 decp = pk2(DEC, DEC);

    for (int t=0;t<NS;t++){
        // load k_t (coalesced float4, L1/L2-shared across all warps of batch)
        u64 kp[8];
        #pragma unroll
        for (int c=0;c<4;c++){
            F4U kv; kv.f = kb[(size_t)t*(NHH/4) + c*32];
            kp[2*c]   = kv.u[0];
            kp[2*c+1] = kv.u[1];
        }

        // dots with OLD mem (ikv uses mem from previous step)
        u64 a0 = 0ULL, a1 = 0ULL;
        #pragma unroll
        for (int p=0;p<8;p++){
            a0 = fma2(m0[p], kp[p], a0);
            a1 = fma2(m1[p], kp[p], a1);
        }
        float x0,y0,x1,y1;
        up2(a0,x0,y0); up2(a1,x1,y1);
        u64 red = pk2(x0+y0, x1+y1);
        #pragma unroll
        for (int o=16;o;o>>=1)
            red = add2(red, __shfl_xor_sync(0xffffffffu, red, o));
        float dot0, dot1; up2(red, dot0, dot1);

        // kt' update (scaled trace: kt' = d*kt' + k)
        #pragma unroll
        for (int p=0;p<8;p++) kt[p] = fma2(kt[p], decp, kp[p]);

        // scalar chain (replicated across lanes, deterministic)
        float iv0 = __ldg(ivb + (size_t)t*N2H);
        float iv1 = __ldg(ivb + (size_t)t*N2H + 1);
        vs0 = fmaf(vs0, ALPHA, fmaf(0.2f, dot0, iv0));
        vs1 = fmaf(vs1, ALPHA, fmaf(0.2f, dot1, iv1));
        float v0 = tanhf(vs0), v1 = tanhf(vs1);
        vt0 = fmaf(OMD, v0, DEC*vt0);
        vt1 = fmaf(OMD, v1, DEC*vt1);
        if (lane == 0)
            *(float2*)(vb + (size_t)t*NHH) = make_float2(v0, v1);

        // mem row update: mem = (1 - LR*vt^2)*mem + (LR*(1-d)*vt)*kt'
        float c10 = fmaf(-LR*vt0, vt0, 1.0f);
        float c11 = fmaf(-LR*vt1, vt1, 1.0f);
        float c20 = (LR*OMD)*vt0;
        float c21 = (LR*OMD)*vt1;
        u64 c1p0=pk2(c10,c10), c2p0=pk2(c20,c20);
        u64 c1p1=pk2(c11,c11), c2p1=pk2(c21,c21);
        #pragma unroll
        for (int p=0;p<8;p++){
            m0[p] = fma2(m0[p], c1p0, mul2(kt[p], c2p0));
            m1[p] = fma2(m1[p], c1p1, mul2(kt[p], c2p1));
        }
    }

    // write final mem rows
    float* mo = mem_out + ((size_t)b*NHH + row0)*NHH + lane*4;
    #pragma unroll
    for (int c=0;c<4;c++){
        F4U u0; u0.u[0]=m0[2*c]; u0.u[1]=m0[2*c+1];
        *(float4*)(mo + c*128) = u0.f;
        F4U u1; u1.u[0]=m1[2*c]; u1.u[1]=m1[2*c+1];
        *(float4*)(mo + NHH + c*128) = u1.f;
    }
}

// ---------------------------------------------------------------------------
extern "C" void kernel_launch(void* const* d_in, const int* in_sizes, int n_in,
                              void* d_out, int out_size)
{
    const float* x = (const float*)d_in[0];   // [64,256,256]
    const float* W = (const float*)d_in[1];   // [1024,256]
    float* out = (float*)d_out;
    float* mem_out  = out;                                    // [64,512,512]
    float* keys_out = out + (size_t)NB*NHH*NHH;               // [64,256,512]
    float* vals_out = keys_out + (size_t)NB*NS*NHH;           // [64,256,512]

    dim3 g1(N2H/BN, NM/BM);                 // (8, 128)
    sgemm_kernel<<<g1, 256>>>(x, W);
    trace_kernel<<<(NB*NHH)/256, 256>>>(keys_out);
    recur_kernel<<<dim3(32, NB), 256>>>(keys_out, mem_out, vals_out);
}

// round 2
// speedup vs baseline: 1.5609x; 1.5609x over previous
#include <cuda_runtime.h>

#define NB 64
#define NS 256
#define NI 256
#define NHH 512
#define N2H 1024
#define NM (NB*NS)

// Scratch for the pre-activation GEMM output i = x @ W^T   [16384 x 1024], 64MB
static __device__ float g_C[(size_t)NM * N2H];

typedef unsigned long long u64;
__device__ __forceinline__ u64 pk2(float lo, float hi){ u64 r; asm("mov.b64 %0,{%1,%2};" : "=l"(r) : "f"(lo), "f"(hi)); return r; }
__device__ __forceinline__ void up2(u64 a, float& lo, float& hi){ asm("mov.b64 {%0,%1},%2;" : "=f"(lo), "=f"(hi) : "l"(a)); }
__device__ __forceinline__ u64 fma2(u64 a, u64 b, u64 c){ u64 d; asm("fma.rn.f32x2 %0,%1,%2,%3;" : "=l"(d) : "l"(a), "l"(b), "l"(c)); return d; }
__device__ __forceinline__ u64 mul2(u64 a, u64 b){ u64 d; asm("mul.rn.f32x2 %0,%1,%2;" : "=l"(d) : "l"(a), "l"(b)); return d; }
__device__ __forceinline__ u64 add2(u64 a, u64 b){ u64 d; asm("add.rn.f32x2 %0,%1,%2;" : "=l"(d) : "l"(a), "l"(b)); return d; }

// tanh(x) = 1 - 2/(exp(2x)+1); MUFU.EX2 + MUFU.RCP path, rel err ~1e-6.
// Saturates correctly for |x| large (exp->inf -> 1; exp->0 -> -1).
__device__ __forceinline__ float fast_tanh(float x){
    float z = __expf(2.0f * x);
    return 1.0f - __fdividef(2.0f, z + 1.0f);
}

union F4U { float4 f; u64 u[2]; };

// ---------------------------------------------------------------------------
// Kernel 1: SGEMM  C[m][n] = sum_k x[m][k] * W[n][k]
// M=16384, N=1024, K=256.  128x128 tile, BK=32, 256 threads, 8x8 per thread.
// ---------------------------------------------------------------------------
#define BM 128
#define BN 128
#define BK 32

__global__ __launch_bounds__(256) void sgemm_kernel(const float* __restrict__ A,
                                                    const float* __restrict__ W)
{
    __shared__ float As[BK][BM+4];
    __shared__ float Bs[BK][BN+4];
    const int tid = threadIdx.x;
    const int m0 = blockIdx.y * BM;
    const int n0 = blockIdx.x * BN;
    const int tr = tid >> 4;        // 0..15
    const int tc = tid & 15;        // 0..15

    float acc[8][8];
    #pragma unroll
    for (int i=0;i<8;i++)
        #pragma unroll
        for (int j=0;j<8;j++) acc[i][j]=0.f;

    const int lr = tid >> 3;          // 0..31
    const int lc = (tid & 7) << 2;    // 0,4,...,28

    for (int k0=0; k0<NI; k0+=BK){
        #pragma unroll
        for (int h=0; h<4; h++){
            int r = lr + h*32;
            float4 av = *(const float4*)(A + (size_t)(m0+r)*NI + k0 + lc);
            As[lc+0][r]=av.x; As[lc+1][r]=av.y; As[lc+2][r]=av.z; As[lc+3][r]=av.w;
            float4 bv = *(const float4*)(W + (size_t)(n0+r)*NI + k0 + lc);
            Bs[lc+0][r]=bv.x; Bs[lc+1][r]=bv.y; Bs[lc+2][r]=bv.z; Bs[lc+3][r]=bv.w;
        }
        __syncthreads();
        #pragma unroll
        for (int kk=0;kk<BK;kk++){
            float a[8], bb[8];
            *(float4*)(a)    = *(const float4*)(&As[kk][tr*8]);
            *(float4*)(a+4)  = *(const float4*)(&As[kk][tr*8+4]);
            *(float4*)(bb)   = *(const float4*)(&Bs[kk][tc*8]);
            *(float4*)(bb+4) = *(const float4*)(&Bs[kk][tc*8+4]);
            #pragma unroll
            for (int i=0;i<8;i++)
                #pragma unroll
                for (int j=0;j<8;j++)
                    acc[i][j] = fmaf(a[i], bb[j], acc[i][j]);
        }
        __syncthreads();
    }
    #pragma unroll
    for (int i=0;i<8;i++){
        float* cptr = g_C + (size_t)(m0 + tr*8 + i)*N2H + n0 + tc*8;
        *(float4*)(cptr)   = make_float4(acc[i][0],acc[i][1],acc[i][2],acc[i][3]);
        *(float4*)(cptr+4) = make_float4(acc[i][4],acc[i][5],acc[i][6],acc[i][7]);
    }
}

// ---------------------------------------------------------------------------
// Kernel 2: k-trace precompute. Per (b,h): ks recurrence + tanh -> keys output.
// ---------------------------------------------------------------------------
__global__ __launch_bounds__(256) void trace_kernel(float* __restrict__ keys_out)
{
    int gid = blockIdx.x*blockDim.x + threadIdx.x;   // 0..32767
    int b = gid >> 9;
    int h = gid & 511;
    const float* c = g_C + (size_t)b*NS*N2H + h;      // ik column
    float* ko = keys_out + (size_t)b*NS*NHH + h;
    const float ALPHA = 0.9048374180359595f;
    float ks = 0.f;
    #pragma unroll 8
    for (int t=0;t<NS;t++){
        ks = fmaf(ks, ALPHA, __ldg(c + (size_t)t*N2H));
        ko[(size_t)t*NHH] = fast_tanh(ks);
    }
}

// ---------------------------------------------------------------------------
// Kernel 3: main recurrence. One warp owns 4 mem rows (scaled: m'' = mem/P),
// 16 floats (8 packed u64) per lane per row, all in registers.
// Per step (single fma2 per element for the update thanks to rescaling):
//   dot_r   = P_r * (m''_r . k_t)          (butterfly-reduced, packed pairs)
//   kt'     = d*kt' + k                    (shared across rows)
//   scalars: vs,v=tanh,vt,c1=1-LR*vt^2 ; P*=c1 ; Q*=~1/c1 (3-fma series)
//   m''_r  += kt' * (Q_r*vt_r)             (8 fma2)
// Grid: (8 row-groups, 64 batches) x 128 threads (4 warps x 4 rows = 16 rows).
// ---------------------------------------------------------------------------
__global__ __launch_bounds__(128) void recur_kernel(const float* __restrict__ keys,
                                                    float* __restrict__ mem_out,
                                                    float* __restrict__ vals_out)
{
    const int b    = blockIdx.y;
    const int rg   = blockIdx.x;       // 0..31
    const int warp = threadIdx.x >> 5; // 0..3
    const int lane = threadIdx.x & 31;
    const int row0 = rg*16 + warp*4;

    const float ALPHA = 0.9048374180359595f;   // exp(-1/10)
    const float DEC   = 0.9512294245007140f;   // exp(-1/20)
    const float OMD   = 0.0487705754992860f;   // 1 - DEC
    const float LR    = 0.01f;

    u64 m[4][8], kt[8];
    #pragma unroll
    for (int r=0;r<4;r++)
        #pragma unroll
        for (int p=0;p<8;p++) m[r][p]=0ULL;
    #pragma unroll
    for (int p=0;p<8;p++) kt[p]=0ULL;

    float vs[4]={0,0,0,0}, vt[4]={0,0,0,0};
    float P[4]={1.f,1.f,1.f,1.f};
    float Q[4]={LR*OMD, LR*OMD, LR*OMD, LR*OMD};

    const float4* kb  = (const float4*)(keys + (size_t)b*NS*NHH) + lane;
    const float4* ivb = (const float4*)(g_C + (size_t)b*NS*N2H + NHH + row0);
    float4*       vb  = (float4*)(vals_out + (size_t)b*NS*NHH + row0);

    const u64 decp = pk2(DEC, DEC);

    // prefetch t=0
    float4 kf[4];
    #pragma unroll
    for (int c=0;c<4;c++) kf[c] = __ldg(&kb[c*32]);
    float4 ivf = __ldg(&ivb[0]);

    for (int t=0;t<NS;t++){
        // commit prefetched k, iv
        u64 kp[8];
        #pragma unroll
        for (int c=0;c<4;c++){
            F4U kv; kv.f = kf[c];
            kp[2*c] = kv.u[0]; kp[2*c+1] = kv.u[1];
        }
        float ivv[4] = {ivf.x, ivf.y, ivf.z, ivf.w};

        // prefetch next step (clamped)
        int tn = (t+1 < NS) ? (t+1) : t;
        #pragma unroll
        for (int c=0;c<4;c++) kf[c] = __ldg(&kb[(size_t)tn*(NHH/4) + c*32]);
        ivf = __ldg(&ivb[(size_t)tn*(N2H/4)]);

        // dots with current (scaled) mem
        u64 a[4];
        #pragma unroll
        for (int r=0;r<4;r++){
            u64 acc = 0ULL;
            #pragma unroll
            for (int p=0;p<8;p++) acc = fma2(m[r][p], kp[p], acc);
            a[r] = acc;
        }

        // kt' update (independent of reduce -> overlaps shfl latency)
        #pragma unroll
        for (int p=0;p<8;p++) kt[p] = fma2(kt[p], decp, kp[p]);

        // horizontal + butterfly allreduce (two packed chains in parallel)
        float x,y;
        up2(a[0],x,y); float h0 = x+y;
        up2(a[1],x,y); float h1 = x+y;
        up2(a[2],x,y); float h2 = x+y;
        up2(a[3],x,y); float h3 = x+y;
        u64 r01 = pk2(h0,h1), r23 = pk2(h2,h3);
        #pragma unroll
        for (int o=16;o;o>>=1){
            r01 = add2(r01, __shfl_xor_sync(0xffffffffu, r01, o));
            r23 = add2(r23, __shfl_xor_sync(0xffffffffu, r23, o));
        }
        float dot[4];
        up2(r01, dot[0], dot[1]);
        up2(r23, dot[2], dot[3]);

        // scalar chains (warp-uniform, replicated across lanes)
        float v[4];
        #pragma unroll
        for (int r=0;r<4;r++){
            float d  = P[r]*dot[r];
            vs[r] = fmaf(vs[r], ALPHA, fmaf(0.2f, d, ivv[r]));
            v[r]  = fast_tanh(vs[r]);
            vt[r] = fmaf(OMD, v[r], DEC*vt[r]);
            float e  = LR*vt[r]*vt[r];
            float c1 = 1.0f - e;
            P[r] *= c1;
            // 1/c1 ~= 1 + e + e^2 + e^3  (err ~ e^4 <= 1e-8)
            float inv = fmaf(e, fmaf(e, (1.0f + e), 1.0f), 1.0f);
            Q[r] *= inv;
        }

        if (lane == 0)
            vb[(size_t)t*(NHH/4)] = make_float4(v[0], v[1], v[2], v[3]);

        // scaled mem update: m''_r += kt' * (Q_r * vt_r)   (1 fma2/elem-pair)
        #pragma unroll
        for (int r=0;r<4;r++){
            float w = Q[r]*vt[r];
            u64 wp = pk2(w, w);
            #pragma unroll
            for (int p=0;p<8;p++) m[r][p] = fma2(kt[p], wp, m[r][p]);
        }
    }

    // write final mem rows: mem = P_r * m''_r
    #pragma unroll
    for (int r=0;r<4;r++){
        u64 Pp = pk2(P[r], P[r]);
        float* mo = mem_out + ((size_t)b*NHH + row0 + r)*NHH + lane*4;
        #pragma unroll
        for (int c=0;c<4;c++){
            F4U u;
            u.u[0] = mul2(m[r][2*c],   Pp);
            u.u[1] = mul2(m[r][2*c+1], Pp);
            *(float4*)(mo + c*128) = u.f;
        }
    }
}

// ---------------------------------------------------------------------------
extern "C" void kernel_launch(void* const* d_in, const int* in_sizes, int n_in,
                              void* d_out, int out_size)
{
    const float* x = (const float*)d_in[0];   // [64,256,256]
    const float* W = (const float*)d_in[1];   // [1024,256]
    float* out = (float*)d_out;
    float* mem_out  = out;                                    // [64,512,512]
    float* keys_out = out + (size_t)NB*NHH*NHH;               // [64,256,512]
    float* vals_out = keys_out + (size_t)NB*NS*NHH;           // [64,256,512]

    dim3 g1(N2H/BN, NM/BM);                 // (8, 128)
    sgemm_kernel<<<g1, 256>>>(x, W);
    trace_kernel<<<(NB*NHH)/256, 256>>>(keys_out);
    recur_kernel<<<dim3(32, NB), 128>>>(keys_out, mem_out, vals_out);
}